// round 13
// baseline (speedup 1.0000x reference)
#include <cuda_runtime.h>
#include <cuda_fp16.h>
#include <cstdint>

#define BATCH 4096
#define NE    64
#define EPSV  1e-5f

// ===================== device scratch (no runtime alloc) ====================
__device__ __align__(16) float g_buf0[BATCH * 256];
__device__ __align__(16) float g_buf1[BATCH * 256];
__device__ __align__(16) float g_buf2[BATCH * 256];
__device__ __align__(16) float g_w   [BATCH * NE];
__device__ float g_sum;

// activation fp16 (max 4096 x 256)
__device__ __align__(16) __half g_Zf[BATCH * 256];

// fp16 weights: enc0(1M) enc1(4M) dec0(4M) dec1(1M) = 10.5M elems
#define OFF_ENC0 0
#define OFF_ENC1 1048576
#define OFF_DEC0 5242880
#define OFF_DEC1 9437184
#define W_TOTAL  10485760
__device__ __align__(16) __half g_Wf[W_TOTAL];

// ===================== PTX helpers (base sm_103 target only) ===============
__device__ __forceinline__ uint32_t smem_u32(const void* p) {
    uint32_t a;
    asm("{ .reg .u64 t; cvta.to.shared.u64 t, %1; cvt.u32.u64 %0, t; }"
        : "=r"(a) : "l"(p));
    return a;
}

#define LDSM4(r, a) \
    asm volatile("ldmatrix.sync.aligned.m8n8.x4.shared.b16 {%0,%1,%2,%3}, [%4];" \
        : "=r"((r)[0]), "=r"((r)[1]), "=r"((r)[2]), "=r"((r)[3]) : "r"(a))

#define MMA16816H(d, a, b0v, b1v) \
    asm volatile("mma.sync.aligned.m16n8k16.row.col.f32.f16.f16.f32 " \
        "{%0,%1,%2,%3}, {%4,%5,%6,%7}, {%8,%9}, {%0,%1,%2,%3};" \
        : "+f"((d)[0]), "+f"((d)[1]), "+f"((d)[2]), "+f"((d)[3]) \
        : "r"((a)[0]), "r"((a)[1]), "r"((a)[2]), "r"((a)[3]), "r"(b0v), "r"(b1v))

#define CP_ASYNC16(dst, src) \
    asm volatile("cp.async.cg.shared.global [%0], [%1], 16;" :: "r"(dst), "l"(src))
#define CP_COMMIT() asm volatile("cp.async.commit_group;" ::: "memory")
#define CP_WAIT2()  asm volatile("cp.async.wait_group 2;" ::: "memory")
#define CP_WAIT1()  asm volatile("cp.async.wait_group 1;" ::: "memory")
#define CP_WAIT0()  asm volatile("cp.async.wait_group 0;" ::: "memory")

// ============ convert fp32 -> fp16 (8 elems per thread) ====================
__device__ __forceinline__ uint4 cvt8(const float* __restrict__ src8) {
    float4 v0 = reinterpret_cast<const float4*>(src8)[0];
    float4 v1 = reinterpret_cast<const float4*>(src8)[1];
    __half2 h0 = __floats2half2_rn(v0.x, v0.y);
    __half2 h1 = __floats2half2_rn(v0.z, v0.w);
    __half2 h2 = __floats2half2_rn(v1.x, v1.y);
    __half2 h3 = __floats2half2_rn(v1.z, v1.w);
    return make_uint4(*reinterpret_cast<uint32_t*>(&h0),
                      *reinterpret_cast<uint32_t*>(&h1),
                      *reinterpret_cast<uint32_t*>(&h2),
                      *reinterpret_cast<uint32_t*>(&h3));
}

// ---- all 4 expert weights + x0 converted in ONE kernel (8 elems/thread) ---
#define N8_0 (OFF_ENC1 / 8)
#define N8_1 (OFF_DEC0 / 8)
#define N8_2 (OFF_DEC1 / 8)
#define N8_3 (W_TOTAL / 8)
#define N8_4 (N8_3 + BATCH * 64 / 8)
__global__ __launch_bounds__(256)
void cvt_all_kernel(const float* __restrict__ W0, const float* __restrict__ W1,
                    const float* __restrict__ W2, const float* __restrict__ W3,
                    const float* __restrict__ X0,
                    __half* __restrict__ Wf, __half* __restrict__ Zf) {
    int i = blockIdx.x * 256 + threadIdx.x;
    const float* src; int base; __half* dst; int di;
    if      (i < N8_0) { src = W0; base = 0;    dst = Wf; di = i; }
    else if (i < N8_1) { src = W1; base = N8_0; dst = Wf; di = i; }
    else if (i < N8_2) { src = W2; base = N8_1; dst = Wf; di = i; }
    else if (i < N8_3) { src = W3; base = N8_2; dst = Wf; di = i; }
    else               { src = X0; base = N8_3; dst = Zf; di = i - N8_3; }
    reinterpret_cast<uint4*>(dst)[di] = cvt8(src + (size_t)(i - base) * 8);
}

// ======== MNet GEMM, split-K, no bias (cancels in BN), atomicAdd ===========
__global__ __launch_bounds__(256)
void gemm_splitk_kernel(const float* __restrict__ X, const float* __restrict__ W,
                        float* __restrict__ C, int K, int N, int KC) {
    const int BM = 64, BN = 64, BK = 16, TM = 4, TN = 4;
    __shared__ __align__(16) float As[BK][BM];
    __shared__ __align__(16) float Bs[BK][BN];
    int tid  = threadIdx.x;
    int n0   = blockIdx.x * BN;
    int m0   = blockIdx.y * BM;
    int kb   = blockIdx.z * KC;
    int tn   = tid & 15, tm = tid >> 4;
    int row0 = tm * TM, col0 = tn * TN;
    int lr   = tid >> 2, ls = tid & 3;
    float acc[TM][TN] = {};
    for (int k0 = kb; k0 < kb + KC; k0 += BK) {
        float4 av = *reinterpret_cast<const float4*>(&X[(size_t)(m0 + lr) * K + k0 + ls * 4]);
        As[ls*4+0][lr] = av.x; As[ls*4+1][lr] = av.y; As[ls*4+2][lr] = av.z; As[ls*4+3][lr] = av.w;
        float4 bv = *reinterpret_cast<const float4*>(&W[(size_t)(n0 + lr) * K + k0 + ls * 4]);
        Bs[ls*4+0][lr] = bv.x; Bs[ls*4+1][lr] = bv.y; Bs[ls*4+2][lr] = bv.z; Bs[ls*4+3][lr] = bv.w;
        __syncthreads();
        #pragma unroll
        for (int kk = 0; kk < BK; ++kk) {
            float a[TM], b[TN];
            float4 va = *reinterpret_cast<const float4*>(&As[kk][row0]);
            a[0]=va.x; a[1]=va.y; a[2]=va.z; a[3]=va.w;
            float4 vb = *reinterpret_cast<const float4*>(&Bs[kk][col0]);
            b[0]=vb.x; b[1]=vb.y; b[2]=vb.z; b[3]=vb.w;
            #pragma unroll
            for (int i = 0; i < TM; i++)
                #pragma unroll
                for (int j = 0; j < TN; j++)
                    acc[i][j] = fmaf(a[i], b[j], acc[i][j]);
        }
        __syncthreads();
    }
    #pragma unroll
    for (int i = 0; i < TM; i++)
        #pragma unroll
        for (int j = 0; j < TN; j++)
            atomicAdd(&C[(size_t)(m0 + row0 + i) * N + n0 + col0 + j], acc[i][j]);
}

// ============ BN + PReLU in place (MNet layers 1,2) ========================
__global__ __launch_bounds__(256)
void bn_prelu_kernel(float* __restrict__ X, const float* __restrict__ g,
                     const float* __restrict__ be, const float* __restrict__ aP,
                     int C) {
    __shared__ float s1[256], s2[256];
    int tid = threadIdx.x;
    int col = blockIdx.x * 2 + (tid & 1);
    int r0  = tid >> 1;
    float sum = 0.f, sq = 0.f;
    for (int r = r0; r < BATCH; r += 128) {
        float v = X[(size_t)r * C + col];
        sum += v; sq += v * v;
    }
    s1[tid] = sum; s2[tid] = sq;
    __syncthreads();
    #pragma unroll
    for (int off = 128; off >= 2; off >>= 1) {
        if (tid < off) { s1[tid] += s1[tid + off]; s2[tid] += s2[tid + off]; }
        __syncthreads();
    }
    float mean = s1[tid & 1] * (1.f / BATCH);
    float var  = s2[tid & 1] * (1.f / BATCH) - mean * mean;
    float sc   = g[col] * rsqrtf(var + EPSV);
    float sh   = be[col] - mean * sc;
    float a    = aP[0];
    for (int r = r0; r < BATCH; r += 128) {
        float v = X[(size_t)r * C + col] * sc + sh;
        X[(size_t)r * C + col] = (v >= 0.f) ? v : a * v;
    }
}

// ==== BN + PReLU in place + accumulate global sum (MNet layer 3 -> w) ======
__global__ __launch_bounds__(256)
void bn_prelu_wsum_kernel(float* __restrict__ X, const float* __restrict__ g,
                          const float* __restrict__ be, const float* __restrict__ aP,
                          int C) {
    __shared__ float s1[256], s2[256];
    int tid = threadIdx.x;
    int col = blockIdx.x * 2 + (tid & 1);
    int r0  = tid >> 1;
    float sum = 0.f, sq = 0.f;
    for (int r = r0; r < BATCH; r += 128) {
        float v = X[(size_t)r * C + col];
        sum += v; sq += v * v;
    }
    s1[tid] = sum; s2[tid] = sq;
    __syncthreads();
    #pragma unroll
    for (int off = 128; off >= 2; off >>= 1) {
        if (tid < off) { s1[tid] += s1[tid + off]; s2[tid] += s2[tid + off]; }
        __syncthreads();
    }
    float mean = s1[tid & 1] * (1.f / BATCH);
    float var  = s2[tid & 1] * (1.f / BATCH) - mean * mean;
    float sc   = g[col] * rsqrtf(var + EPSV);
    float sh   = be[col] - mean * sc;
    float a    = aP[0];
    float wsum = 0.f;
    for (int r = r0; r < BATCH; r += 128) {
        float v = X[(size_t)r * C + col] * sc + sh;
        v = (v >= 0.f) ? v : a * v;
        X[(size_t)r * C + col] = v;
        wsum += v;
    }
    __syncthreads();
    s1[tid] = wsum;
    __syncthreads();
    #pragma unroll
    for (int off = 128; off; off >>= 1) {
        if (tid < off) s1[tid] += s1[tid + off];
        __syncthreads();
    }
    if (tid == 0) atomicAdd(&g_sum, s1[0]);
}

// ====== BN + PReLU fused with fp16 convert (expert path) ===================
__global__ __launch_bounds__(256)
void bn_prelu_h_kernel(const float* __restrict__ X, const float* __restrict__ g,
                       const float* __restrict__ be, const float* __restrict__ aP,
                       int C, __half* __restrict__ Zf) {
    __shared__ float s1[256], s2[256];
    int tid = threadIdx.x;
    int col = blockIdx.x * 2 + (tid & 1);
    int r0  = tid >> 1;
    float sum = 0.f, sq = 0.f;
    for (int r = r0; r < BATCH; r += 128) {
        float v = X[(size_t)r * C + col];
        sum += v; sq += v * v;
    }
    s1[tid] = sum; s2[tid] = sq;
    __syncthreads();
    #pragma unroll
    for (int off = 128; off >= 2; off >>= 1) {
        if (tid < off) { s1[tid] += s1[tid + off]; s2[tid] += s2[tid + off]; }
        __syncthreads();
    }
    float mean = s1[tid & 1] * (1.f / BATCH);
    float var  = s2[tid & 1] * (1.f / BATCH) - mean * mean;
    float sc   = g[col] * rsqrtf(var + EPSV);
    float sh   = be[col] - mean * sc;
    float a    = aP[0];
    for (int r = r0; r < BATCH; r += 128) {
        float v = X[(size_t)r * C + col] * sc + sh;
        v = (v >= 0.f) ? v : a * v;
        Zf[(size_t)r * C + col] = __float2half_rn(v);
    }
}

// ===================== mma.sync expert GEMM (fp16) =========================
// accO[b,o] = sum_e (w[b,e]/sum) * (z[b,:] . W[e,o,:] + bias[e,o])
// BM=128, BN templated (128 or 64); 8 warps as 4M x 2N, warp tile 32 x BN/2.
// 4-stage cp.async ring, one __syncthreads per chunk; bias folded into accE;
// out must be zero-initialized; split-K over experts + atomicAdd.
template<int IDIM, int BN, int NCTA>
__global__ __launch_bounds__(256, NCTA)
void expert_mma_kernel(const __half* __restrict__ Zf,
                       const __half* __restrict__ Wf,
                       const float* __restrict__ w,
                       const float* __restrict__ bias,
                       float* __restrict__ out,
                       int O, int eper) {
    constexpr int RS    = 80;                 // padded row stride (bytes)
    constexpr int Ao    = 0;
    constexpr int Bo    = 128 * RS;           // A region: 128 rows
    constexpr int STAGE = (128 + BN) * RS;
    constexpr int CPE   = IDIM / 32;          // chunks per expert
    constexpr int P     = BN / 32;            // 16-col LDSM groups per warp
    constexpr int NT    = BN / 16;            // n8-tiles per warp

    extern __shared__ char smem[];
    uint32_t sb = smem_u32(smem);

    int tid  = threadIdx.x;
    int lane = tid & 31, wid = tid >> 5;
    int wy = wid >> 1, wx = wid & 1;          // 4 M-warps x 2 N-warps
    int m0 = blockIdx.y * 128;
    int n0 = blockIdx.x * BN;
    int e0 = blockIdx.z * eper;
    float inv = 1.f / g_sum;
    const int nc = eper * CPE;

    auto load_chunk = [&](int c, int buf) {
        int e  = e0 + c / CPE;
        int i0 = (c % CPE) * 32;
        uint32_t stg = sb + buf * STAGE;
        // A: 128 rows x 32 fp16 = 512 x 16B
        #pragma unroll
        for (int it = 0; it < 2; ++it) {
            int idx = tid + it * 256;
            int row = idx >> 2, ch = idx & 3;
            const __half* src = Zf + (size_t)(m0 + row) * IDIM + i0 + ch * 8;
            CP_ASYNC16(stg + Ao + row * RS + ch * 16, src);
        }
        // B: BN rows x 32 fp16 = BN*4 x 16B
        #pragma unroll
        for (int it = 0; it < BN / 64; ++it) {
            int idx = tid + it * 256;
            int row = idx >> 2, ch = idx & 3;
            const __half* src = Wf + ((size_t)e * O + n0 + row) * IDIM + i0 + ch * 8;
            CP_ASYNC16(stg + Bo + row * RS + ch * 16, src);
        }
        CP_COMMIT();
    };

    float accE[2][NT][4];
    float accO[2][NT][4] = {};
    int g   = lane >> 2;
    int tig = lane & 3;

    auto set_bias = [&](int e) {
        #pragma unroll
        for (int nt = 0; nt < NT; ++nt) {
            int col = n0 + wx * (BN / 2) + nt * 8 + tig * 2;
            float2 bv = *reinterpret_cast<const float2*>(&bias[(size_t)e * O + col]);
            #pragma unroll
            for (int mt = 0; mt < 2; ++mt) {
                accE[mt][nt][0] = bv.x; accE[mt][nt][1] = bv.y;
                accE[mt][nt][2] = bv.x; accE[mt][nt][3] = bv.y;
            }
        }
    };
    set_bias(e0);

    // ldmatrix address constants
    int arow  = lane & 15;
    int acolb = (lane >> 4) * 16;
    int nrow  = (lane & 7) + ((lane >> 4) << 3);
    int bcolb = ((lane >> 3) & 1) * 16;

    // prologue: fill 3 of 4 stages
    load_chunk(0, 0);
    if (nc > 1) load_chunk(1, 1);
    if (nc > 2) load_chunk(2, 2);

    int buf = 0;
    for (int c = 0; c < nc; ++c) {
        if      (c + 2 < nc) CP_WAIT2();
        else if (c + 1 < nc) CP_WAIT1();
        else                 CP_WAIT0();
        __syncthreads();                      // single barrier per chunk

        uint32_t stg = sb + buf * STAGE;
        #pragma unroll
        for (int kk = 0; kk < 2; ++kk) {
            uint32_t a_f[2][4];
            #pragma unroll
            for (int mt = 0; mt < 2; ++mt) {
                uint32_t ra = stg + Ao + (wy*32 + mt*16 + arow) * RS + kk*32 + acolb;
                LDSM4(a_f[mt], ra);
            }
            uint32_t b_f[P][4];
            #pragma unroll
            for (int p = 0; p < P; ++p) {
                uint32_t rb = stg + Bo + (wx*(BN/2) + p*16 + nrow) * RS + kk*32 + bcolb;
                LDSM4(b_f[p], rb);
            }
            #pragma unroll
            for (int mt = 0; mt < 2; ++mt)
                #pragma unroll
                for (int p = 0; p < P; ++p)
                    #pragma unroll
                    for (int h = 0; h < 2; ++h)
                        MMA16816H(accE[mt][p*2 + h], a_f[mt],
                                  b_f[p][h*2], b_f[p][h*2+1]);
        }

        // issue loads for chunk c+3 into the stage retired at chunk c-1
        if (c + 3 < nc) {
            int nb = buf + 3; if (nb >= 4) nb -= 4;
            load_chunk(c + 3, nb);
        }

        // expert boundary: fold w[b,e]*inv into output accumulator
        if (((c + 1) & (CPE - 1)) == 0) {
            int e = e0 + c / CPE;
            float wv0[2], wv1[2];
            #pragma unroll
            for (int mt = 0; mt < 2; ++mt) {
                int r = m0 + wy*32 + mt*16 + g;
                wv0[mt] = w[(size_t)r * NE + e] * inv;
                wv1[mt] = w[(size_t)(r + 8) * NE + e] * inv;
            }
            #pragma unroll
            for (int mt = 0; mt < 2; ++mt)
                #pragma unroll
                for (int nt = 0; nt < NT; ++nt) {
                    accO[mt][nt][0] = fmaf(wv0[mt], accE[mt][nt][0], accO[mt][nt][0]);
                    accO[mt][nt][1] = fmaf(wv0[mt], accE[mt][nt][1], accO[mt][nt][1]);
                    accO[mt][nt][2] = fmaf(wv1[mt], accE[mt][nt][2], accO[mt][nt][2]);
                    accO[mt][nt][3] = fmaf(wv1[mt], accE[mt][nt][3], accO[mt][nt][3]);
                }
            if (c + 1 < nc) set_bias(e + 1);
        }

        if (++buf >= 4) buf -= 4;
    }

    // ---- epilogue: atomicAdd into zero-initialized out ----
    #pragma unroll
    for (int mt = 0; mt < 2; ++mt)
        #pragma unroll
        for (int nt = 0; nt < NT; ++nt) {
            int row = m0 + wy*32 + mt*16 + g;
            int col = n0 + wx*(BN/2) + nt*8 + tig*2;
            float* p0 = out + (size_t)row * O + col;
            atomicAdd(p0,     accO[mt][nt][0]);
            atomicAdd(p0 + 1, accO[mt][nt][1]);
            float* p1 = p0 + (size_t)8 * O;
            atomicAdd(p1,     accO[mt][nt][2]);
            atomicAdd(p1 + 1, accO[mt][nt][3]);
        }
}

// ===========================================================================
extern "C" void kernel_launch(void* const* d_in, const int* in_sizes, int n_in,
                              void* d_out, int out_size) {
    const float* m0    = (const float*)d_in[0];
    const float* x0    = (const float*)d_in[1];
    const float* mW1   = (const float*)d_in[2];
    const float* mg1   = (const float*)d_in[4];
    const float* mbe1  = (const float*)d_in[5];
    const float* ma1   = (const float*)d_in[6];
    const float* mW2   = (const float*)d_in[7];
    const float* mg2   = (const float*)d_in[9];
    const float* mbe2  = (const float*)d_in[10];
    const float* ma2   = (const float*)d_in[11];
    const float* mW3   = (const float*)d_in[12];
    const float* mg3   = (const float*)d_in[14];
    const float* mbe3  = (const float*)d_in[15];
    const float* ma3   = (const float*)d_in[16];
    const float* Wenc0 = (const float*)d_in[17];
    const float* benc0 = (const float*)d_in[18];
    const float* Wenc1 = (const float*)d_in[19];
    const float* benc1 = (const float*)d_in[20];
    const float* Wdec0 = (const float*)d_in[21];
    const float* bdec0 = (const float*)d_in[22];
    const float* Wdec1 = (const float*)d_in[23];
    const float* bdec1 = (const float*)d_in[24];
    const float* bng   = (const float*)d_in[25];
    const float* bnb   = (const float*)d_in[26];
    const float* aP    = (const float*)d_in[27];
    float* out = (float*)d_out;

    float *b0, *b1, *b2, *wb, *sumP;
    __half *Wf, *Zf;
    cudaGetSymbolAddress((void**)&b0, g_buf0);
    cudaGetSymbolAddress((void**)&b1, g_buf1);
    cudaGetSymbolAddress((void**)&b2, g_buf2);
    cudaGetSymbolAddress((void**)&wb, g_w);
    cudaGetSymbolAddress((void**)&sumP, g_sum);
    cudaGetSymbolAddress((void**)&Wf, g_Wf);
    cudaGetSymbolAddress((void**)&Zf, g_Zf);

    const int SMEM128 = 4 * (128 + 128) * 80;   // 81920
    const int SMEM64  = 4 * (128 +  64) * 80;   // 61440
    cudaFuncSetAttribute(expert_mma_kernel<64, 128, 1>,
                         cudaFuncAttributeMaxDynamicSharedMemorySize, SMEM128);
    cudaFuncSetAttribute(expert_mma_kernel<256, 128, 1>,
                         cudaFuncAttributeMaxDynamicSharedMemorySize, SMEM128);
    cudaFuncSetAttribute(expert_mma_kernel<256, 64, 2>,
                         cudaFuncAttributeMaxDynamicSharedMemorySize, SMEM64);

    // ---- convert expert weights + x0 to fp16 (one kernel) ----
    cvt_all_kernel<<<N8_4 / 256, 256>>>(Wenc0, Wenc1, Wdec0, Wdec1, x0, Wf, Zf);

    // ---- MNet: 3x (Linear(split-K, bias cancels in BN) -> BN -> PReLU) ----
    cudaMemsetAsync(b0, 0, BATCH * 256 * sizeof(float));
    gemm_splitk_kernel<<<dim3(4, 64, 2), 256>>>(m0, mW1, b0, 128, 256, 64);
    bn_prelu_kernel<<<128, 256>>>(b0, mg1, mbe1, ma1, 256);
    cudaMemsetAsync(b1, 0, BATCH * 128 * sizeof(float));
    gemm_splitk_kernel<<<dim3(2, 64, 4), 256>>>(b0, mW2, b1, 256, 128, 64);
    bn_prelu_kernel<<<64, 256>>>(b1, mg2, mbe2, ma2, 128);
    cudaMemsetAsync(wb, 0, BATCH * 64 * sizeof(float));
    cudaMemsetAsync(sumP, 0, sizeof(float));
    gemm_splitk_kernel<<<dim3(1, 64, 2), 256>>>(b1, mW3, wb, 128, 64, 64);
    bn_prelu_wsum_kernel<<<32, 256>>>(wb, mg3, mbe3, ma3, 64);

    // ---- encoder layer 0: x0[4096,64] -> b2[4096,256] ----
    cudaMemsetAsync(b2, 0, BATCH * 256 * sizeof(float));
    expert_mma_kernel<64, 128, 1><<<dim3(2, 32, 4), 256, SMEM128>>>(
        Zf, Wf + OFF_ENC0, wb, benc0, b2, 256, 16);
    bn_prelu_h_kernel<<<128, 256>>>(b2, bng, bnb, aP, 256, Zf);

    // ---- encoder layer 1: -> b0 ----
    cudaMemsetAsync(b0, 0, BATCH * 256 * sizeof(float));
    expert_mma_kernel<256, 128, 1><<<dim3(2, 32, 4), 256, SMEM128>>>(
        Zf, Wf + OFF_ENC1, wb, benc1, b0, 256, 16);
    bn_prelu_h_kernel<<<128, 256>>>(b0, bng, bnb, aP, 256, Zf);

    // ---- decoder layer 0: -> b1 ----
    cudaMemsetAsync(b1, 0, BATCH * 256 * sizeof(float));
    expert_mma_kernel<256, 128, 1><<<dim3(2, 32, 4), 256, SMEM128>>>(
        Zf, Wf + OFF_DEC0, wb, bdec0, b1, 256, 16);
    bn_prelu_h_kernel<<<128, 256>>>(b1, bng, bnb, aP, 256, Zf);

    // ---- decoder layer 1 (no BN/PReLU): -> out [4096,64] ----
    cudaMemsetAsync(out, 0, BATCH * 64 * sizeof(float));
    expert_mma_kernel<256, 64, 2><<<dim3(1, 32, 8), 256, SMEM64>>>(
        Zf, Wf + OFF_DEC1, wb, bdec1, out, 64, 8);
}

// round 14
// speedup vs baseline: 1.1162x; 1.1162x over previous
#include <cuda_runtime.h>
#include <cuda_fp16.h>
#include <cstdint>

#define BATCH 4096
#define NE    64
#define EPSV  1e-5f

// ===================== device scratch (no runtime alloc) ====================
__device__ __align__(16) float g_buf0[BATCH * 256];
__device__ __align__(16) float g_buf1[BATCH * 256];
__device__ __align__(16) float g_buf2[BATCH * 256];
__device__ __align__(16) float g_w   [BATCH * NE];
__device__ float g_sum;

// activation fp16 (max 4096 x 256)
__device__ __align__(16) __half g_Zf[BATCH * 256];

// fp16 weights: enc0(1M) enc1(4M) dec0(4M) dec1(1M) = 10.5M elems
#define OFF_ENC0 0
#define OFF_ENC1 1048576
#define OFF_DEC0 5242880
#define OFF_DEC1 9437184
#define W_TOTAL  10485760
__device__ __align__(16) __half g_Wf[W_TOTAL];

// ===================== PTX helpers (base sm_103 target only) ===============
__device__ __forceinline__ uint32_t smem_u32(const void* p) {
    uint32_t a;
    asm("{ .reg .u64 t; cvta.to.shared.u64 t, %1; cvt.u32.u64 %0, t; }"
        : "=r"(a) : "l"(p));
    return a;
}

#define LDSM4(r, a) \
    asm volatile("ldmatrix.sync.aligned.m8n8.x4.shared.b16 {%0,%1,%2,%3}, [%4];" \
        : "=r"((r)[0]), "=r"((r)[1]), "=r"((r)[2]), "=r"((r)[3]) : "r"(a))

#define MMA16816H(d, a, b0v, b1v) \
    asm volatile("mma.sync.aligned.m16n8k16.row.col.f32.f16.f16.f32 " \
        "{%0,%1,%2,%3}, {%4,%5,%6,%7}, {%8,%9}, {%0,%1,%2,%3};" \
        : "+f"((d)[0]), "+f"((d)[1]), "+f"((d)[2]), "+f"((d)[3]) \
        : "r"((a)[0]), "r"((a)[1]), "r"((a)[2]), "r"((a)[3]), "r"(b0v), "r"(b1v))

#define CP_ASYNC16(dst, src) \
    asm volatile("cp.async.cg.shared.global [%0], [%1], 16;" :: "r"(dst), "l"(src))
#define CP_COMMIT() asm volatile("cp.async.commit_group;" ::: "memory")
#define CP_WAIT1()  asm volatile("cp.async.wait_group 1;" ::: "memory")
#define CP_WAIT0()  asm volatile("cp.async.wait_group 0;" ::: "memory")

// ============ convert fp32 -> fp16 (8 elems per thread) ====================
__device__ __forceinline__ uint4 cvt8(const float* __restrict__ src8) {
    float4 v0 = reinterpret_cast<const float4*>(src8)[0];
    float4 v1 = reinterpret_cast<const float4*>(src8)[1];
    __half2 h0 = __floats2half2_rn(v0.x, v0.y);
    __half2 h1 = __floats2half2_rn(v0.z, v0.w);
    __half2 h2 = __floats2half2_rn(v1.x, v1.y);
    __half2 h3 = __floats2half2_rn(v1.z, v1.w);
    return make_uint4(*reinterpret_cast<uint32_t*>(&h0),
                      *reinterpret_cast<uint32_t*>(&h1),
                      *reinterpret_cast<uint32_t*>(&h2),
                      *reinterpret_cast<uint32_t*>(&h3));
}

// ---- all 4 expert weights + x0 converted in ONE kernel (8 elems/thread) ---
#define N8_0 (OFF_ENC1 / 8)
#define N8_1 (OFF_DEC0 / 8)
#define N8_2 (OFF_DEC1 / 8)
#define N8_3 (W_TOTAL / 8)
#define N8_4 (N8_3 + BATCH * 64 / 8)
__global__ __launch_bounds__(256)
void cvt_all_kernel(const float* __restrict__ W0, const float* __restrict__ W1,
                    const float* __restrict__ W2, const float* __restrict__ W3,
                    const float* __restrict__ X0,
                    __half* __restrict__ Wf, __half* __restrict__ Zf) {
    int i = blockIdx.x * 256 + threadIdx.x;
    const float* src; int base; __half* dst; int di;
    if      (i < N8_0) { src = W0; base = 0;    dst = Wf; di = i; }
    else if (i < N8_1) { src = W1; base = N8_0; dst = Wf; di = i; }
    else if (i < N8_2) { src = W2; base = N8_1; dst = Wf; di = i; }
    else if (i < N8_3) { src = W3; base = N8_2; dst = Wf; di = i; }
    else               { src = X0; base = N8_3; dst = Zf; di = i - N8_3; }
    reinterpret_cast<uint4*>(dst)[di] = cvt8(src + (size_t)(i - base) * 8);
}

// ======== MNet GEMM, split-K, no bias (cancels in BN), atomicAdd ===========
__global__ __launch_bounds__(256)
void gemm_splitk_kernel(const float* __restrict__ X, const float* __restrict__ W,
                        float* __restrict__ C, int K, int N, int KC) {
    const int BM = 64, BN = 64, BK = 16, TM = 4, TN = 4;
    __shared__ __align__(16) float As[BK][BM];
    __shared__ __align__(16) float Bs[BK][BN];
    int tid  = threadIdx.x;
    int n0   = blockIdx.x * BN;
    int m0   = blockIdx.y * BM;
    int kb   = blockIdx.z * KC;
    int tn   = tid & 15, tm = tid >> 4;
    int row0 = tm * TM, col0 = tn * TN;
    int lr   = tid >> 2, ls = tid & 3;
    float acc[TM][TN] = {};
    for (int k0 = kb; k0 < kb + KC; k0 += BK) {
        float4 av = *reinterpret_cast<const float4*>(&X[(size_t)(m0 + lr) * K + k0 + ls * 4]);
        As[ls*4+0][lr] = av.x; As[ls*4+1][lr] = av.y; As[ls*4+2][lr] = av.z; As[ls*4+3][lr] = av.w;
        float4 bv = *reinterpret_cast<const float4*>(&W[(size_t)(n0 + lr) * K + k0 + ls * 4]);
        Bs[ls*4+0][lr] = bv.x; Bs[ls*4+1][lr] = bv.y; Bs[ls*4+2][lr] = bv.z; Bs[ls*4+3][lr] = bv.w;
        __syncthreads();
        #pragma unroll
        for (int kk = 0; kk < BK; ++kk) {
            float a[TM], b[TN];
            float4 va = *reinterpret_cast<const float4*>(&As[kk][row0]);
            a[0]=va.x; a[1]=va.y; a[2]=va.z; a[3]=va.w;
            float4 vb = *reinterpret_cast<const float4*>(&Bs[kk][col0]);
            b[0]=vb.x; b[1]=vb.y; b[2]=vb.z; b[3]=vb.w;
            #pragma unroll
            for (int i = 0; i < TM; i++)
                #pragma unroll
                for (int j = 0; j < TN; j++)
                    acc[i][j] = fmaf(a[i], b[j], acc[i][j]);
        }
        __syncthreads();
    }
    #pragma unroll
    for (int i = 0; i < TM; i++)
        #pragma unroll
        for (int j = 0; j < TN; j++)
            atomicAdd(&C[(size_t)(m0 + row0 + i) * N + n0 + col0 + j], acc[i][j]);
}

// ============ BN + PReLU in place (MNet layers 1,2) ========================
__global__ __launch_bounds__(256)
void bn_prelu_kernel(float* __restrict__ X, const float* __restrict__ g,
                     const float* __restrict__ be, const float* __restrict__ aP,
                     int C) {
    __shared__ float s1[256], s2[256];
    int tid = threadIdx.x;
    int col = blockIdx.x * 2 + (tid & 1);
    int r0  = tid >> 1;
    float sum = 0.f, sq = 0.f;
    for (int r = r0; r < BATCH; r += 128) {
        float v = X[(size_t)r * C + col];
        sum += v; sq += v * v;
    }
    s1[tid] = sum; s2[tid] = sq;
    __syncthreads();
    #pragma unroll
    for (int off = 128; off >= 2; off >>= 1) {
        if (tid < off) { s1[tid] += s1[tid + off]; s2[tid] += s2[tid + off]; }
        __syncthreads();
    }
    float mean = s1[tid & 1] * (1.f / BATCH);
    float var  = s2[tid & 1] * (1.f / BATCH) - mean * mean;
    float sc   = g[col] * rsqrtf(var + EPSV);
    float sh   = be[col] - mean * sc;
    float a    = aP[0];
    for (int r = r0; r < BATCH; r += 128) {
        float v = X[(size_t)r * C + col] * sc + sh;
        X[(size_t)r * C + col] = (v >= 0.f) ? v : a * v;
    }
}

// ==== BN + PReLU in place + accumulate global sum (MNet layer 3 -> w) ======
__global__ __launch_bounds__(256)
void bn_prelu_wsum_kernel(float* __restrict__ X, const float* __restrict__ g,
                          const float* __restrict__ be, const float* __restrict__ aP,
                          int C) {
    __shared__ float s1[256], s2[256];
    int tid = threadIdx.x;
    int col = blockIdx.x * 2 + (tid & 1);
    int r0  = tid >> 1;
    float sum = 0.f, sq = 0.f;
    for (int r = r0; r < BATCH; r += 128) {
        float v = X[(size_t)r * C + col];
        sum += v; sq += v * v;
    }
    s1[tid] = sum; s2[tid] = sq;
    __syncthreads();
    #pragma unroll
    for (int off = 128; off >= 2; off >>= 1) {
        if (tid < off) { s1[tid] += s1[tid + off]; s2[tid] += s2[tid + off]; }
        __syncthreads();
    }
    float mean = s1[tid & 1] * (1.f / BATCH);
    float var  = s2[tid & 1] * (1.f / BATCH) - mean * mean;
    float sc   = g[col] * rsqrtf(var + EPSV);
    float sh   = be[col] - mean * sc;
    float a    = aP[0];
    float wsum = 0.f;
    for (int r = r0; r < BATCH; r += 128) {
        float v = X[(size_t)r * C + col] * sc + sh;
        v = (v >= 0.f) ? v : a * v;
        X[(size_t)r * C + col] = v;
        wsum += v;
    }
    __syncthreads();
    s1[tid] = wsum;
    __syncthreads();
    #pragma unroll
    for (int off = 128; off; off >>= 1) {
        if (tid < off) s1[tid] += s1[tid + off];
        __syncthreads();
    }
    if (tid == 0) atomicAdd(&g_sum, s1[0]);
}

// ====== BN + PReLU fused with fp16 convert (expert path) ===================
__global__ __launch_bounds__(256)
void bn_prelu_h_kernel(const float* __restrict__ X, const float* __restrict__ g,
                       const float* __restrict__ be, const float* __restrict__ aP,
                       int C, __half* __restrict__ Zf) {
    __shared__ float s1[256], s2[256];
    int tid = threadIdx.x;
    int col = blockIdx.x * 2 + (tid & 1);
    int r0  = tid >> 1;
    float sum = 0.f, sq = 0.f;
    for (int r = r0; r < BATCH; r += 128) {
        float v = X[(size_t)r * C + col];
        sum += v; sq += v * v;
    }
    s1[tid] = sum; s2[tid] = sq;
    __syncthreads();
    #pragma unroll
    for (int off = 128; off >= 2; off >>= 1) {
        if (tid < off) { s1[tid] += s1[tid + off]; s2[tid] += s2[tid + off]; }
        __syncthreads();
    }
    float mean = s1[tid & 1] * (1.f / BATCH);
    float var  = s2[tid & 1] * (1.f / BATCH) - mean * mean;
    float sc   = g[col] * rsqrtf(var + EPSV);
    float sh   = be[col] - mean * sc;
    float a    = aP[0];
    for (int r = r0; r < BATCH; r += 128) {
        float v = X[(size_t)r * C + col] * sc + sh;
        v = (v >= 0.f) ? v : a * v;
        Zf[(size_t)r * C + col] = __float2half_rn(v);
    }
}

// ===================== mma.sync expert GEMM (fp16) =========================
// accO[b,o] = sum_e (w[b,e]/sum) * (z[b,:] . W[e,o,:] + bias[e,o])
// K-chunk = 64 fp16 (4 k16 steps); 3-stage cp.async ring, one barrier/chunk.
// w (pre-scaled by 1/sum) and bias for this CTA's experts staged in static
// SMEM once -> boundary folds use LDS only (no global stalls).
// out must be zero-initialized; split-K over experts + atomicAdd.
template<int IDIM, int BN, int NCTA>
__global__ __launch_bounds__(256, NCTA)
void expert_mma_kernel(const __half* __restrict__ Zf,
                       const __half* __restrict__ Wf,
                       const float* __restrict__ w,
                       const float* __restrict__ bias,
                       float* __restrict__ out,
                       int O, int eper) {
    constexpr int RS    = 144;                // 128B data + 16B pad per row
    constexpr int Ao    = 0;
    constexpr int Bo    = 128 * RS;
    constexpr int STAGE = (128 + BN) * RS;
    constexpr int CPE   = IDIM / 64;          // chunks per expert (1 or 4)
    constexpr int P     = BN / 32;            // B LDSM groups per warp per kk
    constexpr int NT    = BN / 16;            // n8-tiles per warp

    __shared__ float wS[128 * 16];            // w*inv, [row][eLocal] stride 16
    __shared__ float bS[16 * BN];             // bias,  [eLocal][col]
    extern __shared__ char smem[];
    uint32_t sb = smem_u32(smem);

    int tid  = threadIdx.x;
    int lane = tid & 31, wid = tid >> 5;
    int wy = wid >> 1, wx = wid & 1;          // 4 M-warps x 2 N-warps
    int m0 = blockIdx.y * 128;
    int n0 = blockIdx.x * BN;
    int e0 = blockIdx.z * eper;
    const int nc = eper * CPE;

    // ---- stage w*inv and bias for this CTA's expert range ----
    {
        float inv = 1.f / g_sum;
        for (int i = tid; i < 128 * eper; i += 256) {
            int r = i / eper, el = i - r * eper;
            wS[r * 16 + el] = w[(size_t)(m0 + r) * NE + e0 + el] * inv;
        }
        for (int i = tid; i < eper * BN; i += 256) {
            int el = i / BN, col = i - el * BN;
            bS[el * BN + col] = bias[(size_t)(e0 + el) * O + n0 + col];
        }
    }

    auto load_chunk = [&](int c, int buf) {
        int e  = e0 + c / CPE;
        int i0 = (c % CPE) * 64;
        uint32_t stg = sb + buf * STAGE;
        // A: 128 rows x 64 fp16 (128B) = 1024 x 16B -> 4 per thread
        #pragma unroll
        for (int it = 0; it < 4; ++it) {
            int idx = tid + it * 256;
            int row = idx >> 3, ch = idx & 7;
            const __half* src = Zf + (size_t)(m0 + row) * IDIM + i0 + ch * 8;
            CP_ASYNC16(stg + Ao + row * RS + ch * 16, src);
        }
        // B: BN rows x 64 fp16 = BN*8 x 16B
        #pragma unroll
        for (int it = 0; it < BN / 32; ++it) {
            int idx = tid + it * 256;
            int row = idx >> 3, ch = idx & 7;
            const __half* src = Wf + ((size_t)e * O + n0 + row) * IDIM + i0 + ch * 8;
            CP_ASYNC16(stg + Bo + row * RS + ch * 16, src);
        }
        CP_COMMIT();
    };

    float accE[2][NT][4];
    float accO[2][NT][4] = {};
    int g   = lane >> 2;
    int tig = lane & 3;

    auto set_bias = [&](int el) {
        #pragma unroll
        for (int nt = 0; nt < NT; ++nt) {
            int col = wx * (BN / 2) + nt * 8 + tig * 2;
            float b0 = bS[el * BN + col];
            float b1 = bS[el * BN + col + 1];
            #pragma unroll
            for (int mt = 0; mt < 2; ++mt) {
                accE[mt][nt][0] = b0; accE[mt][nt][1] = b1;
                accE[mt][nt][2] = b0; accE[mt][nt][3] = b1;
            }
        }
    };

    // ldmatrix address constants
    int arow  = lane & 15;
    int acolb = (lane >> 4) * 16;
    int nrow  = (lane & 7) + ((lane >> 4) << 3);
    int bcolb = ((lane >> 3) & 1) * 16;

    // prologue: fill 2 of 3 stages; barrier covers the wS/bS staging too
    load_chunk(0, 0);
    if (nc > 1) load_chunk(1, 1);
    __syncthreads();
    set_bias(0);

    int buf = 0;
    for (int c = 0; c < nc; ++c) {
        if (c + 1 < nc) CP_WAIT1(); else CP_WAIT0();
        __syncthreads();                      // single barrier per chunk

        uint32_t stg = sb + buf * STAGE;
        #pragma unroll
        for (int kk = 0; kk < 4; ++kk) {
            uint32_t a_f[2][4];
            #pragma unroll
            for (int mt = 0; mt < 2; ++mt) {
                uint32_t ra = stg + Ao + (wy*32 + mt*16 + arow) * RS + kk*32 + acolb;
                LDSM4(a_f[mt], ra);
            }
            uint32_t b_f[P][4];
            #pragma unroll
            for (int p = 0; p < P; ++p) {
                uint32_t rb = stg + Bo + (wx*(BN/2) + p*16 + nrow) * RS + kk*32 + bcolb;
                LDSM4(b_f[p], rb);
            }
            #pragma unroll
            for (int mt = 0; mt < 2; ++mt)
                #pragma unroll
                for (int p = 0; p < P; ++p)
                    #pragma unroll
                    for (int h = 0; h < 2; ++h)
                        MMA16816H(accE[mt][p*2 + h], a_f[mt],
                                  b_f[p][h*2], b_f[p][h*2+1]);
        }

        // issue loads for chunk c+2 into the stage retired at chunk c-1
        if (c + 2 < nc) {
            int nb = buf + 2; if (nb >= 3) nb -= 3;
            load_chunk(c + 2, nb);
        }

        // expert boundary: fold wS into output accumulator (LDS only)
        if (((c + 1) % CPE) == 0) {
            int el = c / CPE;
            float wv0[2], wv1[2];
            #pragma unroll
            for (int mt = 0; mt < 2; ++mt) {
                int r = wy*32 + mt*16 + g;
                wv0[mt] = wS[r * 16 + el];
                wv1[mt] = wS[(r + 8) * 16 + el];
            }
            #pragma unroll
            for (int mt = 0; mt < 2; ++mt)
                #pragma unroll
                for (int nt = 0; nt < NT; ++nt) {
                    accO[mt][nt][0] = fmaf(wv0[mt], accE[mt][nt][0], accO[mt][nt][0]);
                    accO[mt][nt][1] = fmaf(wv0[mt], accE[mt][nt][1], accO[mt][nt][1]);
                    accO[mt][nt][2] = fmaf(wv1[mt], accE[mt][nt][2], accO[mt][nt][2]);
                    accO[mt][nt][3] = fmaf(wv1[mt], accE[mt][nt][3], accO[mt][nt][3]);
                }
            if (c + 1 < nc) set_bias(el + 1);
        }

        if (++buf >= 3) buf -= 3;
    }

    // ---- epilogue: atomicAdd into zero-initialized out ----
    #pragma unroll
    for (int mt = 0; mt < 2; ++mt)
        #pragma unroll
        for (int nt = 0; nt < NT; ++nt) {
            int row = m0 + wy*32 + mt*16 + g;
            int col = n0 + wx*(BN/2) + nt*8 + tig*2;
            float* p0 = out + (size_t)row * O + col;
            atomicAdd(p0,     accO[mt][nt][0]);
            atomicAdd(p0 + 1, accO[mt][nt][1]);
            float* p1 = p0 + (size_t)8 * O;
            atomicAdd(p1,     accO[mt][nt][2]);
            atomicAdd(p1 + 1, accO[mt][nt][3]);
        }
}

// ===========================================================================
extern "C" void kernel_launch(void* const* d_in, const int* in_sizes, int n_in,
                              void* d_out, int out_size) {
    const float* m0    = (const float*)d_in[0];
    const float* x0    = (const float*)d_in[1];
    const float* mW1   = (const float*)d_in[2];
    const float* mg1   = (const float*)d_in[4];
    const float* mbe1  = (const float*)d_in[5];
    const float* ma1   = (const float*)d_in[6];
    const float* mW2   = (const float*)d_in[7];
    const float* mg2   = (const float*)d_in[9];
    const float* mbe2  = (const float*)d_in[10];
    const float* ma2   = (const float*)d_in[11];
    const float* mW3   = (const float*)d_in[12];
    const float* mg3   = (const float*)d_in[14];
    const float* mbe3  = (const float*)d_in[15];
    const float* ma3   = (const float*)d_in[16];
    const float* Wenc0 = (const float*)d_in[17];
    const float* benc0 = (const float*)d_in[18];
    const float* Wenc1 = (const float*)d_in[19];
    const float* benc1 = (const float*)d_in[20];
    const float* Wdec0 = (const float*)d_in[21];
    const float* bdec0 = (const float*)d_in[22];
    const float* Wdec1 = (const float*)d_in[23];
    const float* bdec1 = (const float*)d_in[24];
    const float* bng   = (const float*)d_in[25];
    const float* bnb   = (const float*)d_in[26];
    const float* aP    = (const float*)d_in[27];
    float* out = (float*)d_out;

    float *b0, *b1, *b2, *wb, *sumP;
    __half *Wf, *Zf;
    cudaGetSymbolAddress((void**)&b0, g_buf0);
    cudaGetSymbolAddress((void**)&b1, g_buf1);
    cudaGetSymbolAddress((void**)&b2, g_buf2);
    cudaGetSymbolAddress((void**)&wb, g_w);
    cudaGetSymbolAddress((void**)&sumP, g_sum);
    cudaGetSymbolAddress((void**)&Wf, g_Wf);
    cudaGetSymbolAddress((void**)&Zf, g_Zf);

    const int SMEM128 = 3 * (128 + 128) * 144;   // 110592
    const int SMEM64  = 3 * (128 +  64) * 144;   //  82944
    cudaFuncSetAttribute(expert_mma_kernel<64, 128, 1>,
                         cudaFuncAttributeMaxDynamicSharedMemorySize, SMEM128);
    cudaFuncSetAttribute(expert_mma_kernel<256, 128, 1>,
                         cudaFuncAttributeMaxDynamicSharedMemorySize, SMEM128);
    cudaFuncSetAttribute(expert_mma_kernel<256, 64, 1>,
                         cudaFuncAttributeMaxDynamicSharedMemorySize, SMEM64);

    // ---- convert expert weights + x0 to fp16 (one kernel) ----
    cvt_all_kernel<<<N8_4 / 256, 256>>>(Wenc0, Wenc1, Wdec0, Wdec1, x0, Wf, Zf);

    // ---- MNet: 3x (Linear(split-K, bias cancels in BN) -> BN -> PReLU) ----
    cudaMemsetAsync(b0, 0, BATCH * 256 * sizeof(float));
    gemm_splitk_kernel<<<dim3(4, 64, 2), 256>>>(m0, mW1, b0, 128, 256, 64);
    bn_prelu_kernel<<<128, 256>>>(b0, mg1, mbe1, ma1, 256);
    cudaMemsetAsync(b1, 0, BATCH * 128 * sizeof(float));
    gemm_splitk_kernel<<<dim3(2, 64, 4), 256>>>(b0, mW2, b1, 256, 128, 64);
    bn_prelu_kernel<<<64, 256>>>(b1, mg2, mbe2, ma2, 128);
    cudaMemsetAsync(wb, 0, BATCH * 64 * sizeof(float));
    cudaMemsetAsync(sumP, 0, sizeof(float));
    gemm_splitk_kernel<<<dim3(1, 64, 2), 256>>>(b1, mW3, wb, 128, 64, 64);
    bn_prelu_wsum_kernel<<<32, 256>>>(wb, mg3, mbe3, ma3, 64);

    // ---- encoder layer 0: x0[4096,64] -> b2[4096,256] ----
    cudaMemsetAsync(b2, 0, BATCH * 256 * sizeof(float));
    expert_mma_kernel<64, 128, 1><<<dim3(2, 32, 4), 256, SMEM128>>>(
        Zf, Wf + OFF_ENC0, wb, benc0, b2, 256, 16);
    bn_prelu_h_kernel<<<128, 256>>>(b2, bng, bnb, aP, 256, Zf);

    // ---- encoder layer 1: -> b0 ----
    cudaMemsetAsync(b0, 0, BATCH * 256 * sizeof(float));
    expert_mma_kernel<256, 128, 1><<<dim3(2, 32, 4), 256, SMEM128>>>(
        Zf, Wf + OFF_ENC1, wb, benc1, b0, 256, 16);
    bn_prelu_h_kernel<<<128, 256>>>(b0, bng, bnb, aP, 256, Zf);

    // ---- decoder layer 0: -> b1 ----
    cudaMemsetAsync(b1, 0, BATCH * 256 * sizeof(float));
    expert_mma_kernel<256, 128, 1><<<dim3(2, 32, 4), 256, SMEM128>>>(
        Zf, Wf + OFF_DEC0, wb, bdec0, b1, 256, 16);
    bn_prelu_h_kernel<<<128, 256>>>(b1, bng, bnb, aP, 256, Zf);

    // ---- decoder layer 1 (no BN/PReLU): -> out [4096,64] ----
    cudaMemsetAsync(out, 0, BATCH * 64 * sizeof(float));
    expert_mma_kernel<256, 64, 1><<<dim3(1, 32, 8), 256, SMEM64>>>(
        Zf, Wf + OFF_DEC1, wb, bdec1, out, 64, 8);
}

// round 15
// speedup vs baseline: 1.2158x; 1.0893x over previous
#include <cuda_runtime.h>
#include <cuda_fp16.h>
#include <cstdint>

#define BATCH 4096
#define NE    64
#define EPSV  1e-5f

// ===================== device scratch (no runtime alloc) ====================
__device__ __align__(16) float g_buf0[BATCH * 256];
__device__ __align__(16) float g_buf1[BATCH * 256];
__device__ __align__(16) float g_buf2[BATCH * 256];
__device__ __align__(16) float g_w   [BATCH * NE];
__device__ float g_sum;

// fp16 activations: expert path + MNet ping-pong
__device__ __align__(16) __half g_Zf [BATCH * 256];
__device__ __align__(16) __half g_Zm [BATCH * 256];
__device__ __align__(16) __half g_Zm2[BATCH * 256];

// fp16 expert weights: enc0(1M) enc1(4M) dec0(4M) dec1(1M)
#define OFF_ENC0 0
#define OFF_ENC1 1048576
#define OFF_DEC0 5242880
#define OFF_DEC1 9437184
#define W_TOTAL  10485760
__device__ __align__(16) __half g_Wf[W_TOTAL];

// fp16 MNet weights: W1(256x128) W2(128x256) W3(64x128)
#define OFF_MW1 0
#define OFF_MW2 32768
#define OFF_MW3 65536
__device__ __align__(16) __half g_Wm[73728];

// ===================== PTX helpers (base sm_103 target only) ===============
__device__ __forceinline__ uint32_t smem_u32(const void* p) {
    uint32_t a;
    asm("{ .reg .u64 t; cvta.to.shared.u64 t, %1; cvt.u32.u64 %0, t; }"
        : "=r"(a) : "l"(p));
    return a;
}

#define LDSM4(r, a) \
    asm volatile("ldmatrix.sync.aligned.m8n8.x4.shared.b16 {%0,%1,%2,%3}, [%4];" \
        : "=r"((r)[0]), "=r"((r)[1]), "=r"((r)[2]), "=r"((r)[3]) : "r"(a))

#define MMA16816H(d, a, b0v, b1v) \
    asm volatile("mma.sync.aligned.m16n8k16.row.col.f32.f16.f16.f32 " \
        "{%0,%1,%2,%3}, {%4,%5,%6,%7}, {%8,%9}, {%0,%1,%2,%3};" \
        : "+f"((d)[0]), "+f"((d)[1]), "+f"((d)[2]), "+f"((d)[3]) \
        : "r"((a)[0]), "r"((a)[1]), "r"((a)[2]), "r"((a)[3]), "r"(b0v), "r"(b1v))

#define CP_ASYNC16(dst, src) \
    asm volatile("cp.async.cg.shared.global [%0], [%1], 16;" :: "r"(dst), "l"(src))
#define CP_COMMIT() asm volatile("cp.async.commit_group;" ::: "memory")
#define CP_WAIT1()  asm volatile("cp.async.wait_group 1;" ::: "memory")
#define CP_WAIT0()  asm volatile("cp.async.wait_group 0;" ::: "memory")

// ============ convert fp32 -> fp16 (8 elems per thread) ====================
__device__ __forceinline__ uint4 cvt8(const float* __restrict__ src8) {
    float4 v0 = reinterpret_cast<const float4*>(src8)[0];
    float4 v1 = reinterpret_cast<const float4*>(src8)[1];
    __half2 h0 = __floats2half2_rn(v0.x, v0.y);
    __half2 h1 = __floats2half2_rn(v0.z, v0.w);
    __half2 h2 = __floats2half2_rn(v1.x, v1.y);
    __half2 h3 = __floats2half2_rn(v1.z, v1.w);
    return make_uint4(*reinterpret_cast<uint32_t*>(&h0),
                      *reinterpret_cast<uint32_t*>(&h1),
                      *reinterpret_cast<uint32_t*>(&h2),
                      *reinterpret_cast<uint32_t*>(&h3));
}

// ---- all weights + x0 + m0 converted in ONE kernel (8 elems/thread) -------
#define N8_0 (OFF_ENC1 / 8)
#define N8_1 (OFF_DEC0 / 8)
#define N8_2 (OFF_DEC1 / 8)
#define N8_3 (W_TOTAL / 8)
#define N8_4 (N8_3 + BATCH * 64 / 8)            // x0
#define N8_5 (N8_4 + 32768 / 8)                 // mW1
#define N8_6 (N8_5 + 32768 / 8)                 // mW2
#define N8_7 (N8_6 + 8192 / 8)                  // mW3
#define N8_8 (N8_7 + BATCH * 128 / 8)           // m0 -> 1418240 total
__global__ __launch_bounds__(256)
void cvt_all_kernel(const float* __restrict__ W0, const float* __restrict__ W1,
                    const float* __restrict__ W2, const float* __restrict__ W3,
                    const float* __restrict__ X0,
                    const float* __restrict__ MW1, const float* __restrict__ MW2,
                    const float* __restrict__ MW3, const float* __restrict__ M0,
                    __half* __restrict__ Wf, __half* __restrict__ Zf,
                    __half* __restrict__ Wm, __half* __restrict__ Zm) {
    int i = blockIdx.x * 256 + threadIdx.x;
    const float* src; int base; __half* dst; int di;
    if      (i < N8_0) { src = W0;  base = 0;    dst = Wf; di = i; }
    else if (i < N8_1) { src = W1;  base = N8_0; dst = Wf; di = i; }
    else if (i < N8_2) { src = W2;  base = N8_1; dst = Wf; di = i; }
    else if (i < N8_3) { src = W3;  base = N8_2; dst = Wf; di = i; }
    else if (i < N8_4) { src = X0;  base = N8_3; dst = Zf; di = i - N8_3; }
    else if (i < N8_5) { src = MW1; base = N8_4; dst = Wm; di = i - N8_4 + OFF_MW1 / 8; }
    else if (i < N8_6) { src = MW2; base = N8_5; dst = Wm; di = i - N8_5 + OFF_MW2 / 8; }
    else if (i < N8_7) { src = MW3; base = N8_6; dst = Wm; di = i - N8_6 + OFF_MW3 / 8; }
    else               { src = M0;  base = N8_7; dst = Zm; di = i - N8_7; }
    reinterpret_cast<uint4*>(dst)[di] = cvt8(src + (size_t)(i - base) * 8);
}

// ============ BN + PReLU in place (MNet layer outputs if fp32 needed) ======
__global__ __launch_bounds__(256)
void bn_prelu_wsum_kernel(float* __restrict__ X, const float* __restrict__ g,
                          const float* __restrict__ be, const float* __restrict__ aP,
                          int C) {
    __shared__ float s1[256], s2[256];
    int tid = threadIdx.x;
    int col = blockIdx.x * 2 + (tid & 1);
    int r0  = tid >> 1;
    float sum = 0.f, sq = 0.f;
    for (int r = r0; r < BATCH; r += 128) {
        float v = X[(size_t)r * C + col];
        sum += v; sq += v * v;
    }
    s1[tid] = sum; s2[tid] = sq;
    __syncthreads();
    #pragma unroll
    for (int off = 128; off >= 2; off >>= 1) {
        if (tid < off) { s1[tid] += s1[tid + off]; s2[tid] += s2[tid + off]; }
        __syncthreads();
    }
    float mean = s1[tid & 1] * (1.f / BATCH);
    float var  = s2[tid & 1] * (1.f / BATCH) - mean * mean;
    float sc   = g[col] * rsqrtf(var + EPSV);
    float sh   = be[col] - mean * sc;
    float a    = aP[0];
    float wsum = 0.f;
    for (int r = r0; r < BATCH; r += 128) {
        float v = X[(size_t)r * C + col] * sc + sh;
        v = (v >= 0.f) ? v : a * v;
        X[(size_t)r * C + col] = v;
        wsum += v;
    }
    __syncthreads();
    s1[tid] = wsum;
    __syncthreads();
    #pragma unroll
    for (int off = 128; off; off >>= 1) {
        if (tid < off) s1[tid] += s1[tid + off];
        __syncthreads();
    }
    if (tid == 0) atomicAdd(&g_sum, s1[0]);
}

// ====== BN + PReLU fused with fp16 convert (expert + MNet paths) ===========
__global__ __launch_bounds__(256)
void bn_prelu_h_kernel(const float* __restrict__ X, const float* __restrict__ g,
                       const float* __restrict__ be, const float* __restrict__ aP,
                       int C, __half* __restrict__ Zf) {
    __shared__ float s1[256], s2[256];
    int tid = threadIdx.x;
    int col = blockIdx.x * 2 + (tid & 1);
    int r0  = tid >> 1;
    float sum = 0.f, sq = 0.f;
    for (int r = r0; r < BATCH; r += 128) {
        float v = X[(size_t)r * C + col];
        sum += v; sq += v * v;
    }
    s1[tid] = sum; s2[tid] = sq;
    __syncthreads();
    #pragma unroll
    for (int off = 128; off >= 2; off >>= 1) {
        if (tid < off) { s1[tid] += s1[tid + off]; s2[tid] += s2[tid + off]; }
        __syncthreads();
    }
    float mean = s1[tid & 1] * (1.f / BATCH);
    float var  = s2[tid & 1] * (1.f / BATCH) - mean * mean;
    float sc   = g[col] * rsqrtf(var + EPSV);
    float sh   = be[col] - mean * sc;
    float a    = aP[0];
    for (int r = r0; r < BATCH; r += 128) {
        float v = X[(size_t)r * C + col] * sc + sh;
        v = (v >= 0.f) ? v : a * v;
        Zf[(size_t)r * C + col] = __float2half_rn(v);
    }
}

// ================= dense fp16 tensor GEMM (MNet layers) ====================
// out[b,o] = z[b,:] . W[o,:]  (bias cancels in BN). Direct store epilogue.
template<int KDIM, int BN>
__global__ __launch_bounds__(256, 1)
void dense_mma_kernel(const __half* __restrict__ Zf,
                      const __half* __restrict__ Wf,
                      float* __restrict__ out, int N) {
    constexpr int RS    = 144;
    constexpr int Ao    = 0;
    constexpr int Bo    = 128 * RS;
    constexpr int STAGE = (128 + BN) * RS;
    constexpr int NC    = KDIM / 64;
    constexpr int P     = BN / 32;
    constexpr int NT    = BN / 16;

    extern __shared__ char smem[];
    uint32_t sb = smem_u32(smem);

    int tid  = threadIdx.x;
    int lane = tid & 31, wid = tid >> 5;
    int wy = wid >> 1, wx = wid & 1;
    int m0 = blockIdx.y * 128;
    int n0 = blockIdx.x * BN;

    auto load_chunk = [&](int c, int buf) {
        int i0 = c * 64;
        uint32_t stg = sb + buf * STAGE;
        #pragma unroll
        for (int it = 0; it < 4; ++it) {
            int idx = tid + it * 256;
            int row = idx >> 3, ch = idx & 7;
            const __half* src = Zf + (size_t)(m0 + row) * KDIM + i0 + ch * 8;
            CP_ASYNC16(stg + Ao + row * RS + ch * 16, src);
        }
        #pragma unroll
        for (int it = 0; it < BN / 32; ++it) {
            int idx = tid + it * 256;
            int row = idx >> 3, ch = idx & 7;
            const __half* src = Wf + (size_t)(n0 + row) * KDIM + i0 + ch * 8;
            CP_ASYNC16(stg + Bo + row * RS + ch * 16, src);
        }
        CP_COMMIT();
    };

    float acc[2][NT][4] = {};
    int g   = lane >> 2;
    int tig = lane & 3;
    int arow  = lane & 15;
    int acolb = (lane >> 4) * 16;
    int nrow  = (lane & 7) + ((lane >> 4) << 3);
    int bcolb = ((lane >> 3) & 1) * 16;

    load_chunk(0, 0);
    if (NC > 1) load_chunk(1, 1);

    int buf = 0;
    for (int c = 0; c < NC; ++c) {
        if (c + 1 < NC) CP_WAIT1(); else CP_WAIT0();
        __syncthreads();
        uint32_t stg = sb + buf * STAGE;
        #pragma unroll
        for (int kk = 0; kk < 4; ++kk) {
            uint32_t a_f[2][4];
            #pragma unroll
            for (int mt = 0; mt < 2; ++mt) {
                uint32_t ra = stg + Ao + (wy*32 + mt*16 + arow) * RS + kk*32 + acolb;
                LDSM4(a_f[mt], ra);
            }
            uint32_t b_f[P][4];
            #pragma unroll
            for (int p = 0; p < P; ++p) {
                uint32_t rb = stg + Bo + (wx*(BN/2) + p*16 + nrow) * RS + kk*32 + bcolb;
                LDSM4(b_f[p], rb);
            }
            #pragma unroll
            for (int mt = 0; mt < 2; ++mt)
                #pragma unroll
                for (int p = 0; p < P; ++p)
                    #pragma unroll
                    for (int h = 0; h < 2; ++h)
                        MMA16816H(acc[mt][p*2 + h], a_f[mt],
                                  b_f[p][h*2], b_f[p][h*2+1]);
        }
        if (c + 2 < NC) {
            int nb = buf + 2; if (nb >= 3) nb -= 3;
            load_chunk(c + 2, nb);
        }
        if (++buf >= 3) buf -= 3;
    }

    #pragma unroll
    for (int mt = 0; mt < 2; ++mt)
        #pragma unroll
        for (int nt = 0; nt < NT; ++nt) {
            int row = m0 + wy*32 + mt*16 + g;
            int col = n0 + wx*(BN/2) + nt*8 + tig*2;
            *reinterpret_cast<float2*>(&out[(size_t)row * N + col]) =
                make_float2(acc[mt][nt][0], acc[mt][nt][1]);
            *reinterpret_cast<float2*>(&out[(size_t)(row + 8) * N + col]) =
                make_float2(acc[mt][nt][2], acc[mt][nt][3]);
        }
}

// ===================== mma.sync expert GEMM (fp16) =========================
// accO[b,o] = sum_e (w[b,e]/sum) * (z[b,:] . W[e,o,:] + bias[e,o])
// K-chunk = 64; 3-stage cp.async ring; wS/bS staged in static SMEM;
// out must be zero-initialized; split-K over experts + atomicAdd.
template<int IDIM, int BN, int NCTA>
__global__ __launch_bounds__(256, NCTA)
void expert_mma_kernel(const __half* __restrict__ Zf,
                       const __half* __restrict__ Wf,
                       const float* __restrict__ w,
                       const float* __restrict__ bias,
                       float* __restrict__ out,
                       int O, int eper) {
    constexpr int RS    = 144;
    constexpr int Ao    = 0;
    constexpr int Bo    = 128 * RS;
    constexpr int STAGE = (128 + BN) * RS;
    constexpr int CPE   = IDIM / 64;
    constexpr int P     = BN / 32;
    constexpr int NT    = BN / 16;

    __shared__ float wS[128 * 16];
    __shared__ float bS[16 * BN];
    extern __shared__ char smem[];
    uint32_t sb = smem_u32(smem);

    int tid  = threadIdx.x;
    int lane = tid & 31, wid = tid >> 5;
    int wy = wid >> 1, wx = wid & 1;
    int m0 = blockIdx.y * 128;
    int n0 = blockIdx.x * BN;
    int e0 = blockIdx.z * eper;
    const int nc = eper * CPE;

    {
        float inv = 1.f / g_sum;
        for (int i = tid; i < 128 * eper; i += 256) {
            int r = i / eper, el = i - r * eper;
            wS[r * 16 + el] = w[(size_t)(m0 + r) * NE + e0 + el] * inv;
        }
        for (int i = tid; i < eper * BN; i += 256) {
            int el = i / BN, col = i - el * BN;
            bS[el * BN + col] = bias[(size_t)(e0 + el) * O + n0 + col];
        }
    }

    auto load_chunk = [&](int c, int buf) {
        int e  = e0 + c / CPE;
        int i0 = (c % CPE) * 64;
        uint32_t stg = sb + buf * STAGE;
        #pragma unroll
        for (int it = 0; it < 4; ++it) {
            int idx = tid + it * 256;
            int row = idx >> 3, ch = idx & 7;
            const __half* src = Zf + (size_t)(m0 + row) * IDIM + i0 + ch * 8;
            CP_ASYNC16(stg + Ao + row * RS + ch * 16, src);
        }
        #pragma unroll
        for (int it = 0; it < BN / 32; ++it) {
            int idx = tid + it * 256;
            int row = idx >> 3, ch = idx & 7;
            const __half* src = Wf + ((size_t)e * O + n0 + row) * IDIM + i0 + ch * 8;
            CP_ASYNC16(stg + Bo + row * RS + ch * 16, src);
        }
        CP_COMMIT();
    };

    float accE[2][NT][4];
    float accO[2][NT][4] = {};
    int g   = lane >> 2;
    int tig = lane & 3;

    auto set_bias = [&](int el) {
        #pragma unroll
        for (int nt = 0; nt < NT; ++nt) {
            int col = wx * (BN / 2) + nt * 8 + tig * 2;
            float b0 = bS[el * BN + col];
            float b1 = bS[el * BN + col + 1];
            #pragma unroll
            for (int mt = 0; mt < 2; ++mt) {
                accE[mt][nt][0] = b0; accE[mt][nt][1] = b1;
                accE[mt][nt][2] = b0; accE[mt][nt][3] = b1;
            }
        }
    };

    int arow  = lane & 15;
    int acolb = (lane >> 4) * 16;
    int nrow  = (lane & 7) + ((lane >> 4) << 3);
    int bcolb = ((lane >> 3) & 1) * 16;

    load_chunk(0, 0);
    if (nc > 1) load_chunk(1, 1);
    __syncthreads();
    set_bias(0);

    int buf = 0;
    for (int c = 0; c < nc; ++c) {
        if (c + 1 < nc) CP_WAIT1(); else CP_WAIT0();
        __syncthreads();

        uint32_t stg = sb + buf * STAGE;
        #pragma unroll
        for (int kk = 0; kk < 4; ++kk) {
            uint32_t a_f[2][4];
            #pragma unroll
            for (int mt = 0; mt < 2; ++mt) {
                uint32_t ra = stg + Ao + (wy*32 + mt*16 + arow) * RS + kk*32 + acolb;
                LDSM4(a_f[mt], ra);
            }
            uint32_t b_f[P][4];
            #pragma unroll
            for (int p = 0; p < P; ++p) {
                uint32_t rb = stg + Bo + (wx*(BN/2) + p*16 + nrow) * RS + kk*32 + bcolb;
                LDSM4(b_f[p], rb);
            }
            #pragma unroll
            for (int mt = 0; mt < 2; ++mt)
                #pragma unroll
                for (int p = 0; p < P; ++p)
                    #pragma unroll
                    for (int h = 0; h < 2; ++h)
                        MMA16816H(accE[mt][p*2 + h], a_f[mt],
                                  b_f[p][h*2], b_f[p][h*2+1]);
        }

        if (c + 2 < nc) {
            int nb = buf + 2; if (nb >= 3) nb -= 3;
            load_chunk(c + 2, nb);
        }

        if (((c + 1) % CPE) == 0) {
            int el = c / CPE;
            float wv0[2], wv1[2];
            #pragma unroll
            for (int mt = 0; mt < 2; ++mt) {
                int r = wy*32 + mt*16 + g;
                wv0[mt] = wS[r * 16 + el];
                wv1[mt] = wS[(r + 8) * 16 + el];
            }
            #pragma unroll
            for (int mt = 0; mt < 2; ++mt)
                #pragma unroll
                for (int nt = 0; nt < NT; ++nt) {
                    accO[mt][nt][0] = fmaf(wv0[mt], accE[mt][nt][0], accO[mt][nt][0]);
                    accO[mt][nt][1] = fmaf(wv0[mt], accE[mt][nt][1], accO[mt][nt][1]);
                    accO[mt][nt][2] = fmaf(wv1[mt], accE[mt][nt][2], accO[mt][nt][2]);
                    accO[mt][nt][3] = fmaf(wv1[mt], accE[mt][nt][3], accO[mt][nt][3]);
                }
            if (c + 1 < nc) set_bias(el + 1);
        }

        if (++buf >= 3) buf -= 3;
    }

    #pragma unroll
    for (int mt = 0; mt < 2; ++mt)
        #pragma unroll
        for (int nt = 0; nt < NT; ++nt) {
            int row = m0 + wy*32 + mt*16 + g;
            int col = n0 + wx*(BN/2) + nt*8 + tig*2;
            float* p0 = out + (size_t)row * O + col;
            atomicAdd(p0,     accO[mt][nt][0]);
            atomicAdd(p0 + 1, accO[mt][nt][1]);
            float* p1 = p0 + (size_t)8 * O;
            atomicAdd(p1,     accO[mt][nt][2]);
            atomicAdd(p1 + 1, accO[mt][nt][3]);
        }
}

// ===========================================================================
extern "C" void kernel_launch(void* const* d_in, const int* in_sizes, int n_in,
                              void* d_out, int out_size) {
    const float* m0    = (const float*)d_in[0];
    const float* x0    = (const float*)d_in[1];
    const float* mW1   = (const float*)d_in[2];
    const float* mg1   = (const float*)d_in[4];
    const float* mbe1  = (const float*)d_in[5];
    const float* ma1   = (const float*)d_in[6];
    const float* mW2   = (const float*)d_in[7];
    const float* mg2   = (const float*)d_in[9];
    const float* mbe2  = (const float*)d_in[10];
    const float* ma2   = (const float*)d_in[11];
    const float* mW3   = (const float*)d_in[12];
    const float* mg3   = (const float*)d_in[14];
    const float* mbe3  = (const float*)d_in[15];
    const float* ma3   = (const float*)d_in[16];
    const float* Wenc0 = (const float*)d_in[17];
    const float* benc0 = (const float*)d_in[18];
    const float* Wenc1 = (const float*)d_in[19];
    const float* benc1 = (const float*)d_in[20];
    const float* Wdec0 = (const float*)d_in[21];
    const float* bdec0 = (const float*)d_in[22];
    const float* Wdec1 = (const float*)d_in[23];
    const float* bdec1 = (const float*)d_in[24];
    const float* bng   = (const float*)d_in[25];
    const float* bnb   = (const float*)d_in[26];
    const float* aP    = (const float*)d_in[27];
    float* out = (float*)d_out;

    float *b0, *b1, *b2, *wb, *sumP;
    __half *Wf, *Zf, *Wm, *Zm, *Zm2;
    cudaGetSymbolAddress((void**)&b0, g_buf0);
    cudaGetSymbolAddress((void**)&b1, g_buf1);
    cudaGetSymbolAddress((void**)&b2, g_buf2);
    cudaGetSymbolAddress((void**)&wb, g_w);
    cudaGetSymbolAddress((void**)&sumP, g_sum);
    cudaGetSymbolAddress((void**)&Wf, g_Wf);
    cudaGetSymbolAddress((void**)&Zf, g_Zf);
    cudaGetSymbolAddress((void**)&Wm, g_Wm);
    cudaGetSymbolAddress((void**)&Zm, g_Zm);
    cudaGetSymbolAddress((void**)&Zm2, g_Zm2);

    const int SMEM128 = 3 * (128 + 128) * 144;   // 110592
    const int SMEM64  = 3 * (128 +  64) * 144;   //  82944
    cudaFuncSetAttribute(expert_mma_kernel<64, 128, 1>,
                         cudaFuncAttributeMaxDynamicSharedMemorySize, SMEM128);
    cudaFuncSetAttribute(expert_mma_kernel<256, 128, 1>,
                         cudaFuncAttributeMaxDynamicSharedMemorySize, SMEM128);
    cudaFuncSetAttribute(expert_mma_kernel<256, 64, 1>,
                         cudaFuncAttributeMaxDynamicSharedMemorySize, SMEM64);
    cudaFuncSetAttribute(dense_mma_kernel<128, 128>,
                         cudaFuncAttributeMaxDynamicSharedMemorySize, SMEM128);
    cudaFuncSetAttribute(dense_mma_kernel<256, 128>,
                         cudaFuncAttributeMaxDynamicSharedMemorySize, SMEM128);
    cudaFuncSetAttribute(dense_mma_kernel<128, 64>,
                         cudaFuncAttributeMaxDynamicSharedMemorySize, SMEM64);

    // ---- convert all weights + x0 + m0 to fp16 (one kernel) ----
    cvt_all_kernel<<<N8_8 / 256, 256>>>(Wenc0, Wenc1, Wdec0, Wdec1, x0,
                                        mW1, mW2, mW3, m0, Wf, Zf, Wm, Zm);

    // ---- MNet: 3x (fp16 tensor GEMM -> BN -> PReLU) -> w [4096,64] ----
    dense_mma_kernel<128, 128><<<dim3(2, 32), 256, SMEM128>>>(
        Zm, Wm + OFF_MW1, b0, 256);
    bn_prelu_h_kernel<<<128, 256>>>(b0, mg1, mbe1, ma1, 256, Zm2);
    dense_mma_kernel<256, 128><<<dim3(1, 32), 256, SMEM128>>>(
        Zm2, Wm + OFF_MW2, b1, 128);
    bn_prelu_h_kernel<<<64, 256>>>(b1, mg2, mbe2, ma2, 128, Zm);
    dense_mma_kernel<128, 64><<<dim3(1, 32), 256, SMEM64>>>(
        Zm, Wm + OFF_MW3, wb, 64);
    cudaMemsetAsync(sumP, 0, sizeof(float));
    bn_prelu_wsum_kernel<<<32, 256>>>(wb, mg3, mbe3, ma3, 64);

    // ---- encoder layer 0: x0[4096,64] -> b2[4096,256] ----
    cudaMemsetAsync(b2, 0, BATCH * 256 * sizeof(float));
    expert_mma_kernel<64, 128, 1><<<dim3(2, 32, 4), 256, SMEM128>>>(
        Zf, Wf + OFF_ENC0, wb, benc0, b2, 256, 16);
    bn_prelu_h_kernel<<<128, 256>>>(b2, bng, bnb, aP, 256, Zf);

    // ---- encoder layer 1: -> b0 ----
    cudaMemsetAsync(b0, 0, BATCH * 256 * sizeof(float));
    expert_mma_kernel<256, 128, 1><<<dim3(2, 32, 4), 256, SMEM128>>>(
        Zf, Wf + OFF_ENC1, wb, benc1, b0, 256, 16);
    bn_prelu_h_kernel<<<128, 256>>>(b0, bng, bnb, aP, 256, Zf);

    // ---- decoder layer 0: -> b1 ----
    cudaMemsetAsync(b1, 0, BATCH * 256 * sizeof(float));
    expert_mma_kernel<256, 128, 1><<<dim3(2, 32, 4), 256, SMEM128>>>(
        Zf, Wf + OFF_DEC0, wb, bdec0, b1, 256, 16);
    bn_prelu_h_kernel<<<128, 256>>>(b1, bng, bnb, aP, 256, Zf);

    // ---- decoder layer 1 (no BN/PReLU): -> out [4096,64] ----
    cudaMemsetAsync(out, 0, BATCH * 64 * sizeof(float));
    expert_mma_kernel<256, 64, 1><<<dim3(1, 32, 8), 256, SMEM64>>>(
        Zf, Wf + OFF_DEC1, wb, bdec1, out, 64, 8);
}